// round 17
// baseline (speedup 1.0000x reference)
#include <cuda_runtime.h>
#include <cuda_bf16.h>

#define NB 2
#define NN 2048
#define NF 256
#define NH 8
#define NO 32

typedef unsigned long long ull;

// ---------------- f32x2 packed-math helpers (sm_103a FFMA2 path) --------------
__device__ __forceinline__ void ffma2(ull& d, ull a, ull b) {
    asm("fma.rn.f32x2 %0, %1, %2, %0;" : "+l"(d) : "l"(a), "l"(b));
}
__device__ __forceinline__ void fadd2(ull& d, ull a) {
    asm("add.rn.f32x2 %0, %1, %0;" : "+l"(d) : "l"(a));
}
__device__ __forceinline__ ull pack2(float x, float y) {
    ull r;
    asm("mov.b64 %0, {%1, %2};" : "=l"(r) : "f"(x), "f"(y));
    return r;
}
__device__ __forceinline__ float2 unpack2(ull v) {
    float2 r;
    asm("mov.b64 {%0, %1}, %2;" : "=f"(r.x), "=f"(r.y) : "l"(v));
    return r;
}

// ---------------- cp.async helpers --------------------------------------------
__device__ __forceinline__ void cp16(const void* smem_dst, const void* gsrc) {
    unsigned d = (unsigned)__cvta_generic_to_shared(smem_dst);
    asm volatile("cp.async.cg.shared.global [%0], [%1], 16;" :: "r"(d), "l"(gsrc));
}
#define CP_COMMIT() asm volatile("cp.async.commit_group;")
#define CP_WAIT0()  asm volatile("cp.async.wait_group 0;")
#define CP_WAIT1()  asm volatile("cp.async.wait_group 1;")

// ---------------- scratch (device globals; no allocation allowed) -------------
__device__ __align__(128) float    g_h [NB*NN*NF];   // layer input / stage-B output
__device__ __align__(128) float    g_hA[NB*NN*NF];   // stage-A attention output
__device__ __align__(128) float    g_Wh[NB*NN*NF];   // projected features (V), row-major
__device__ __align__(128) float    g_s1[NB*NH*NN];
__device__ __align__(128) float    g_s2[NB*NH*NN];
__device__ __align__(128) unsigned g_bm[NB*NN*(NN/32)];  // adjacency bitmask

// ---------------- adjacency -> bitmask (runs once) ----------------------------
__global__ void bm_kernel(const int* __restrict__ adj) {
    int wid  = blockIdx.x * 8 + (threadIdx.x >> 5);
    int lane = threadIdx.x & 31;
    int word = wid & 63;
    int row  = wid >> 6;                       // b*NN + i
    int j = word * 32 + lane;
    int a = adj[(size_t)row * NN + j];
    unsigned bits = __ballot_sync(0xffffffffu, a != 0);
    if (lane == 0) g_bm[wid] = bits;
}

// ---------------- GEMM: g_Wh = A[M,256] @ B[256,256] --------------------------
// asel: 0 -> Aext (x), 1 -> g_h, 2 -> g_hA
// bmode 0: B = W_heads[l] head-packed on the fly; bmode 1: B = Bsrc (plain)
__global__ void gemm_kernel(const float* __restrict__ Aext,
                            const float* __restrict__ Bsrc,
                            int asel, int bmode) {
    const float* A = (asel == 0) ? Aext : (asel == 1 ? g_h : g_hA);
    __shared__ __align__(16) float Ast[16][68];   // [k][m], padded
    __shared__ __align__(16) float Bs [16][64];   // [k][n]
    int tid = threadIdx.x;
    int tx = tid & 15, ty = tid >> 4;
    int mbase = blockIdx.y * 64, nbase = blockIdx.x * 64;
    float acc[4][4];
    #pragma unroll
    for (int i = 0; i < 4; i++)
        #pragma unroll
        for (int j = 0; j < 4; j++) acc[i][j] = 0.f;

    int am = tid >> 2, ak = (tid & 3) * 4;
    int bk = tid >> 4, bn = (tid & 15) * 4;
    int c0 = nbase + bn, hh = c0 >> 5, cc = c0 & 31;

    for (int kk = 0; kk < NF; kk += 16) {
        float4 av = *(const float4*)&A[(size_t)(mbase + am) * NF + kk + ak];
        float4 bv;
        if (bmode == 0)   // W_heads[l][h][f][o] with h=c>>5, o=c&31 (cc mult of 4)
            bv = *(const float4*)&Bsrc[((size_t)hh * NF + kk + bk) * NO + cc];
        else
            bv = *(const float4*)&Bsrc[(size_t)(kk + bk) * NF + c0];
        Ast[ak + 0][am] = av.x; Ast[ak + 1][am] = av.y;
        Ast[ak + 2][am] = av.z; Ast[ak + 3][am] = av.w;
        *(float4*)&Bs[bk][bn] = bv;
        __syncthreads();
        #pragma unroll
        for (int k = 0; k < 16; k++) {
            float4 a = *(const float4*)&Ast[k][ty * 4];
            float4 b = *(const float4*)&Bs [k][tx * 4];
            acc[0][0] += a.x * b.x; acc[0][1] += a.x * b.y;
            acc[0][2] += a.x * b.z; acc[0][3] += a.x * b.w;
            acc[1][0] += a.y * b.x; acc[1][1] += a.y * b.y;
            acc[1][2] += a.y * b.z; acc[1][3] += a.y * b.w;
            acc[2][0] += a.z * b.x; acc[2][1] += a.z * b.y;
            acc[2][2] += a.z * b.z; acc[2][3] += a.z * b.w;
            acc[3][0] += a.w * b.x; acc[3][1] += a.w * b.y;
            acc[3][2] += a.w * b.z; acc[3][3] += a.w * b.w;
        }
        __syncthreads();
    }
    #pragma unroll
    for (int i = 0; i < 4; i++) {
        *(float4*)&g_Wh[(size_t)(mbase + ty * 4 + i) * NF + nbase + tx * 4] =
            make_float4(acc[i][0], acc[i][1], acc[i][2], acc[i][3]);
    }
}

// ---------------- s1/s2 for the 8-head stage ----------------------------------
__global__ void sheads_kernel(const float* __restrict__ aheads, int l) {
    int w = threadIdx.x >> 5, lane = threadIdx.x & 31;
    int row = blockIdx.x * 8 + w;          // b*NN + n
    int b = row >> 11, n = row & (NN - 1);
    #pragma unroll
    for (int h = 0; h < NH; h++) {
        float v  = g_Wh[(size_t)row * NF + h * NO + lane];
        float a1 = aheads[((size_t)l * NH + h) * 2 * NO + lane];
        float a2 = aheads[((size_t)l * NH + h) * 2 * NO + NO + lane];
        float p1 = v * a1, p2 = v * a2;
        #pragma unroll
        for (int off = 16; off; off >>= 1) {
            p1 += __shfl_xor_sync(0xffffffffu, p1, off);
            p2 += __shfl_xor_sync(0xffffffffu, p2, off);
        }
        if (lane == 0) {
            g_s1[(b * NH + h) * NN + n] = p1;
            g_s2[(b * NH + h) * NN + n] = p2;
        }
    }
}

// ---------------- s1/s2 for the single-head out stage -------------------------
__global__ void sout_kernel(const float* __restrict__ aout, int l) {
    int w = threadIdx.x >> 5, lane = threadIdx.x & 31;
    int row = blockIdx.x * 8 + w;          // b*NN + n
    float p1 = 0.f, p2 = 0.f;
    #pragma unroll
    for (int k = 0; k < NF / 32; k++) {
        float v = g_Wh[(size_t)row * NF + k * 32 + lane];
        p1 += v * aout[(size_t)l * 2 * NF + k * 32 + lane];
        p2 += v * aout[(size_t)l * 2 * NF + NF + k * 32 + lane];
    }
    #pragma unroll
    for (int off = 16; off; off >>= 1) {
        p1 += __shfl_xor_sync(0xffffffffu, p1, off);
        p2 += __shfl_xor_sync(0xffffffffu, p2, off);
    }
    if (lane == 0) { g_s1[row] = p1; g_s2[row] = p2; }
}

// ---------------- fused attention v10: 4 rows/lane, o-split warps -------------
// Block = 128 rows x 32 o; 8 warps = 2 o-halves (16 o) x 4 j-quarters (32 j).
// Lane carries FOUR rows (row0 + r*32 + lane): each broadcast V LDS.128 feeds
// 8 FFMA2 (4 rows x vv pair) -> 8 FFMA2/LDS, 2x v9. acc = 4x8 ull = 64 regs
// (same as v9). p/exp duplicated per o-half (MUFU ~50% of fma time, hidden).
// Epilogue: two passes over VT-aliased 32KB buffer, 4-warp o-half groups.
#define JT  128

__global__ void __launch_bounds__(256, 2)
attn_kernel(float* __restrict__ oext, int osel,
            int spb, int symul, int elu2) {
    __shared__ __align__(16) float VT[2][JT * NO];   // 2 x 16KB, [buf][j*32+o]
    __shared__ __align__(16) float s2s[NN];          // 8KB
    __shared__ float redl[8][4][32];                 // 4KB (lsum partials)
    __shared__ float redm[8];

    float* out = (osel == 0) ? g_hA : (osel == 1 ? g_h : oext);
    int b = blockIdx.z, y = blockIdx.y;
    int tid = threadIdx.x;
    int w = tid >> 5, lane = tid & 31;
    int oh = w >> 2, jq = w & 3;
    int vb = y * NO;
    int sidx = b * spb + y * symul;
    const float* s1p = g_s1 + (size_t)sidx * NN;
    const float* s2p = g_s2 + (size_t)sidx * NN;
    int row0 = blockIdx.x * 128;
    const float* Vg = g_Wh + ((size_t)b * NN) * NF + vb;

    // ---- prologue: async-load full s2 row (8KB) + V tile 0 ----
    #pragma unroll
    for (int k = 0; k < 2; k++) {
        int q = tid + 256 * k;
        cp16(&s2s[q * 4], s2p + q * 4);
    }
    #pragma unroll
    for (int k = 0; k < 4; k++) {
        int q = tid + 256 * k, j = q >> 3, seg = q & 7;
        cp16(&VT[0][j * NO + seg * 4], Vg + (size_t)j * NF + seg * 4);
    }
    CP_COMMIT();
    const unsigned* bmrow[4];
    unsigned mwcur[4];
    float s1r[4];
    #pragma unroll
    for (int r = 0; r < 4; r++) {
        int row = row0 + r * 32 + lane;
        bmrow[r] = g_bm + ((size_t)(b * NN + row) << 6) + jq;
        mwcur[r] = __ldg(bmrow[r]);
        s1r[r] = s1p[row];
    }
    CP_WAIT0();
    __syncthreads();

    // ---- fused m2 (block max of s2; any upper bound is valid) ----
    float mloc = -3.0e38f;
    for (int i = tid; i < NN; i += 256) mloc = fmaxf(mloc, s2s[i]);
    #pragma unroll
    for (int off = 16; off; off >>= 1)
        mloc = fmaxf(mloc, __shfl_xor_sync(0xffffffffu, mloc, off));
    if (lane == 0) redm[w] = mloc;
    __syncthreads();
    float m2 = redm[0];
    #pragma unroll
    for (int i = 1; i < 8; i++) m2 = fmaxf(m2, redm[i]);

    float cir[4], lsum[4];
    ull acc[4][8];
    #pragma unroll
    for (int r = 0; r < 4; r++) {
        float t = s1r[r] + m2;
        cir[r] = fmaxf(t, 0.2f * t);
        lsum[r] = 0.f;
        #pragma unroll
        for (int q = 0; q < 8; q++) acc[r][q] = 0ull;
    }

    int jloc0 = jq * 32;                 // within-tile j base for this warp

    for (int it = 0; it < NN / JT; it++) {
        int buf = it & 1;
        unsigned mw[4];
        #pragma unroll
        for (int r = 0; r < 4; r++) mw[r] = mwcur[r];
        if (it + 1 < NN / JT) {          // prefetch next tile + next mask words
            const float* Vn = Vg + (size_t)(it + 1) * JT * NF;
            #pragma unroll
            for (int k = 0; k < 4; k++) {
                int q = tid + 256 * k, j = q >> 3, seg = q & 7;
                cp16(&VT[buf ^ 1][j * NO + seg * 4], Vn + (size_t)j * NF + seg * 4);
            }
            CP_COMMIT();
            #pragma unroll
            for (int r = 0; r < 4; r++) mwcur[r] = __ldg(bmrow[r] + (it + 1) * 4);
            CP_WAIT1();
        } else {
            CP_WAIT0();
        }
        __syncthreads();

        const float* s2b = s2s + it * JT + jloc0;
        const float* vbase = &VT[buf][jloc0 * NO + oh * 16];
        #pragma unroll 4
        for (int jj = 0; jj < 32; jj++) {
            float s2v = s2b[jj];
            ull pp[4];
            #pragma unroll
            for (int r = 0; r < 4; r++) {
                float x = s1r[r] + s2v;
                float e = fmaxf(x, 0.2f * x);            // leakyrelu(0.2)
                float p = ((mw[r] >> jj) & 1u) ? __expf(e - cir[r]) : 0.f;
                lsum[r] += p;
                pp[r] = pack2(p, p);
            }
            const ulonglong2* vr = (const ulonglong2*)(vbase + jj * NO);
            #pragma unroll
            for (int q4 = 0; q4 < 4; q4++) {
                ulonglong2 vv = vr[q4];                  // broadcast LDS.128
                #pragma unroll
                for (int r = 0; r < 4; r++) {
                    ffma2(acc[r][2 * q4],     pp[r], vv.x);
                    ffma2(acc[r][2 * q4 + 1], pp[r], vv.y);
                }
            }
        }
        __syncthreads();
    }

    #pragma unroll
    for (int r = 0; r < 4; r++) redl[w][r][lane] = lsum[r];
    __syncthreads();

    // ---- cross-warp reduction: two passes over VT-aliased 32KB buffer ----
    // Pass p covers rows r = 2p, 2p+1. Writer: 8 ulonglong2 slots per lane,
    // swizzled pidx = (slot + lane) & 7. Reader: sum over the 4 warps of each
    // o-half; output o-quad = oh*16 + q4*4.
    ulonglong2* red2 = (ulonglong2*)&VT[0][0];   // 256*8 u2 = 32KB
    #pragma unroll
    for (int p = 0; p < 2; p++) {
        #pragma unroll
        for (int q = 0; q < 2; q++) {
            int r = 2 * p + q;
            #pragma unroll
            for (int q4 = 0; q4 < 4; q4++) {
                int pidx = (q * 4 + q4 + lane) & 7;
                red2[((size_t)w * 32 + lane) * 8 + pidx] =
                    make_ulonglong2(acc[r][2 * q4], acc[r][2 * q4 + 1]);
            }
        }
        __syncthreads();
        {
            int laneR = tid >> 3, g = tid & 7;
            int ohr = g >> 2, q4r = g & 3;
            #pragma unroll
            for (int q = 0; q < 2; q++) {
                int pidx = (q * 4 + q4r + laneR) & 7;
                ull a0 = 0ull, a1 = 0ull;
                #pragma unroll
                for (int ww = 0; ww < 4; ww++) {
                    ulonglong2 vv = red2[((size_t)(ohr * 4 + ww) * 32 + laneR) * 8
                                         + pidx];
                    fadd2(a0, vv.x);
                    fadd2(a1, vv.y);
                }
                int rr = 2 * p + q;
                float l = redl[0][rr][laneR] + redl[1][rr][laneR]
                        + redl[2][rr][laneR] + redl[3][rr][laneR];
                float inv = 1.0f / l;
                float2 p0 = unpack2(a0), p1 = unpack2(a1);
                float v[4] = {p0.x * inv, p0.y * inv, p1.x * inv, p1.y * inv};
                #pragma unroll
                for (int k = 0; k < 4; k++) {
                    float vv2 = v[k];
                    vv2 = (vv2 > 0.f) ? vv2 : (__expf(vv2) - 1.f);           // elu
                    if (elu2) vv2 = (vv2 > 0.f) ? vv2 : (__expf(vv2) - 1.f); // 2nd
                    v[k] = vv2;
                }
                *(float4*)&out[((size_t)(b * NN + row0 + rr * 32 + laneR)) * NF
                               + vb + ohr * 16 + q4r * 4] =
                    make_float4(v[0], v[1], v[2], v[3]);
            }
        }
        if (p == 0) __syncthreads();
    }
}

// ---------------- launch ------------------------------------------------------
extern "C" void kernel_launch(void* const* d_in, const int* in_sizes, int n_in,
                              void* d_out, int out_size) {
    const float* x       = (const float*)d_in[0];
    const int*   adj     = (const int*)  d_in[1];
    const float* W_heads = (const float*)d_in[2];
    const float* a_heads = (const float*)d_in[3];
    const float* W_out   = (const float*)d_in[4];
    const float* a_out   = (const float*)d_in[5];
    float* out = (float*)d_out;

    for (int l = 0; l < 3; l++) {
        // ---- stage A: 8-head GAT ----
        gemm_kernel<<<dim3(4, NB * NN / 64), 256>>>(
            l == 0 ? x : nullptr, W_heads + (size_t)l * NH * NF * NO,
            l == 0 ? 0 : 1, 0);
        sheads_kernel<<<NB * NN / 8, 256>>>(a_heads, l);
        if (l == 0) bm_kernel<<<NB * NN * 64 / 8, 256>>>(adj);
        attn_kernel<<<dim3(NN / 128, 8, NB), 256>>>(nullptr, 0, NH, 1, 0);

        // ---- stage B: single-head out GAT (+extra elu) ----
        gemm_kernel<<<dim3(4, NB * NN / 64), 256>>>(
            nullptr, W_out + (size_t)l * NF * NF, 2, 1);
        sout_kernel<<<NB * NN / 8, 256>>>(a_out, l);
        attn_kernel<<<dim3(NN / 128, 8, NB), 256>>>(
            l == 2 ? out : nullptr, l == 2 ? 2 : 1, 1, 0, 1);
    }
}